// round 13
// baseline (speedup 1.0000x reference)
#include <cuda_runtime.h>
#include <cuda_bf16.h>

#define BATCH    131072
#define INP      5
#define HID      64
#define NEXP     40
#define OUTD     5
#define ROWS     64               // batch rows per block
#define NTHREADS 256
#define NBLK     (BATCH / ROWS)   // 2048

// Per-expert precomputed blob: wh[64][80]bf16 (10240B) | wl (10240B) | bias 64 f32 (256B)
#define BLOB_BYTES 20736
#define KB_STRIDE  160            // bf16 row stride BYTES (80 halves)

// ---- dynamic smem layout (bytes) ----
#define ZH_OFF   0
#define ZL_OFF   10240
#define ST0_OFF  20480            // stage 0 (overlaid by zf in Phase A/B)
#define ST1_OFF  41216            // stage 1 (overlaid by pool in Phase A/B)
#define ACTS_OFF 61952
#define SMEM_TOTAL 62208
#define ZF_STRIDE 66              // fp32 z row stride (floats); zf at ST0 (16896B < 20736)

typedef unsigned int u32;

__device__ __align__(16) unsigned char g_wblob[NEXP][BLOB_BYTES];

// k-permutation: within each k16 block store halves in order (2t,2t+1,2t+8,2t+9)
// so fragment pairs (a0,a2)/(b0,b1) are 8B-contiguous -> one LDS.64.
__device__ __forceinline__ int kperm(int k) {
    return (k & 48) | ((k & 6) << 1) | ((k & 8) >> 2) | (k & 1);
}

__device__ __forceinline__ void mma_bf16(float* c, u32 a0, u32 a1, u32 a2, u32 a3,
                                         u32 b0, u32 b1) {
    asm volatile(
        "mma.sync.aligned.m16n8k16.row.col.f32.bf16.bf16.f32 "
        "{%0,%1,%2,%3}, {%4,%5,%6,%7}, {%8,%9}, {%0,%1,%2,%3};"
        : "+f"(c[0]), "+f"(c[1]), "+f"(c[2]), "+f"(c[3])
        : "r"(a0), "r"(a1), "r"(a2), "r"(a3), "r"(b0), "r"(b1));
}

__device__ __forceinline__ void cpasync16(u32 dst, const void* src) {
    asm volatile("cp.async.cg.shared.global [%0], [%1], 16;" :: "r"(dst), "l"(src));
}
#define CP_COMMIT() asm volatile("cp.async.commit_group;")
#define CP_WAIT1()  asm volatile("cp.async.wait_group 1;")

// ---------------------------------------------------------------------------
// JAX threefry2x32, key = jax.random.key(1) -> (0,1); partitionable counters.
// ---------------------------------------------------------------------------
__device__ __forceinline__ u32 rotl32(u32 x, int d) { return (x << d) | (x >> (32 - d)); }

__device__ __forceinline__ void threefry2x32_key01(u32 c0, u32 c1, u32& o0, u32& o1) {
    const u32 ks0 = 0u, ks1 = 1u, ks2 = 0x1BD11BDBu;
    u32 x0 = c0 + ks0, x1 = c1 + ks1;
#define TFR(r) { x0 += x1; x1 = rotl32(x1, (r)); x1 ^= x0; }
    TFR(13) TFR(15) TFR(26) TFR(6)   x0 += ks1; x1 += ks2 + 1u;
    TFR(17) TFR(29) TFR(16) TFR(24)  x0 += ks2; x1 += ks0 + 2u;
    TFR(13) TFR(15) TFR(26) TFR(6)   x0 += ks0; x1 += ks1 + 3u;
    TFR(17) TFR(29) TFR(16) TFR(24)  x0 += ks1; x1 += ks2 + 4u;
    TFR(13) TFR(15) TFR(26) TFR(6)   x0 += ks2; x1 += ks0 + 5u;
#undef TFR
    o0 = x0; o1 = x1;
}

__device__ __forceinline__ float jax_gumbel32(u32 idx) {
    u32 a, b;
    threefry2x32_key01(0u, idx, a, b);
    u32 bits = a ^ b;
    float f = __uint_as_float(0x3f800000u | (bits >> 9)) - 1.0f;
    float u = fmaxf(f, 1.17549435e-38f);
    return -logf(-logf(u));
}

// ---------------------------------------------------------------------------
// Prep kernel: triz_w -> per-expert blob (bf16 hi/lo split, transposed [f][k],
// k-permuted) + bias. Runs once per launch; deterministic.
// ---------------------------------------------------------------------------
__global__ void prep_kernel(const float* __restrict__ triz_w,
                            const float* __restrict__ triz_b) {
    const int e = blockIdx.x;
    const int q = blockIdx.y;          // k-quarter
    unsigned char* blob = g_wblob[e];
    __nv_bfloat16* wh = (__nv_bfloat16*)blob;
    __nv_bfloat16* wl = (__nv_bfloat16*)(blob + 10240);
    const float* we = triz_w + (size_t)e * HID * HID;

    for (int idx = q * 1024 + threadIdx.x; idx < (q + 1) * 1024; idx += 256) {
        int k = idx >> 6, f = idx & 63;
        float v = we[k * HID + f];
        __nv_bfloat16 hi = __float2bfloat16(v);
        __nv_bfloat16 lo = __float2bfloat16(v - __bfloat162float(hi));
        int off = f * 80 + kperm(k);
        wh[off] = hi;
        wl[off] = lo;
    }
    if (q == 0 && threadIdx.x < HID)
        ((float*)(blob + 20480))[threadIdx.x] = triz_b[e * HID + threadIdx.x];
}

// ---------------------------------------------------------------------------
__global__ __launch_bounds__(NTHREADS)
void trizrl_kernel(const float* __restrict__ x,
                   const float* __restrict__ enc_w, const float* __restrict__ enc_b,
                   const float* __restrict__ pol_w, const float* __restrict__ pol_b,
                   const float* __restrict__ dec_w, const float* __restrict__ dec_b,
                   float* __restrict__ out) {
    extern __shared__ __align__(16) char smem[];
    __nv_bfloat16* zh   = (__nv_bfloat16*)(smem + ZH_OFF);
    __nv_bfloat16* zl   = (__nv_bfloat16*)(smem + ZL_OFF);
    float*         zf   = (float*)(smem + ST0_OFF);   // Phase A/B only
    float*         pool = (float*)(smem + ST1_OFF);   // Phase A/B only
    int*           acts = (int*)(smem + ACTS_OFF);

    float* polw = pool;          // [0:2560)
    float* xs   = pool + 2560;   // [2560:2880)

    // Output: concat(out[B,5], probs[B,40], actions[B], h[B,40,64]) fp32
    float* out_out   = out;
    float* out_probs = out + (size_t)BATCH * OUTD;
    float* out_act   = out_probs + (size_t)BATCH * NEXP;
    float* out_h     = out_act + (size_t)BATCH;

    const int tid  = threadIdx.x;
    const int blk  = blockIdx.x;
    const int brow = blk * ROWS;

    for (int i = tid; i < ROWS * INP; i += NTHREADS)
        xs[i] = x[(size_t)brow * INP + i];
    for (int i = tid; i < HID * NEXP; i += NTHREADS) polw[i] = pol_w[i];
    __syncthreads();

    // ---- Phase A: z = tanh(x@enc_w+enc_b) -> zf (fp32) + zh/zl (bf16 split) ----
    {
        const int j  = tid & (HID - 1);
        const int r0 = tid >> 6;          // 0..3
        const int pj = kperm(j);
        float ew0 = __ldg(&enc_w[0 * HID + j]);
        float ew1 = __ldg(&enc_w[1 * HID + j]);
        float ew2 = __ldg(&enc_w[2 * HID + j]);
        float ew3 = __ldg(&enc_w[3 * HID + j]);
        float ew4 = __ldg(&enc_w[4 * HID + j]);
        float eb  = __ldg(&enc_b[j]);
#pragma unroll
        for (int it = 0; it < ROWS / 4; ++it) {
            int r = it * 4 + r0;
            const float* xr = &xs[r * INP];
            float a = eb;
            a = fmaf(xr[0], ew0, a);
            a = fmaf(xr[1], ew1, a);
            a = fmaf(xr[2], ew2, a);
            a = fmaf(xr[3], ew3, a);
            a = fmaf(xr[4], ew4, a);
            float zv = tanhf(a);
            zf[r * ZF_STRIDE + j] = zv;
            __nv_bfloat16 hi = __float2bfloat16(zv);
            __nv_bfloat16 lo = __float2bfloat16(zv - __bfloat162float(hi));
            zh[r * 80 + pj] = hi;
            zl[r * 80 + pj] = lo;
        }
    }
    __syncthreads();

    // ---- Phase B: logits (exact fp32), gumbel-max categorical, softmax probs ----
    {
        const int r = tid >> 2;
        const int q = tid & 3;
        const int b = brow + r;
        const float* zr = &zf[r * ZF_STRIDE];

        float lg[10];
#pragma unroll
        for (int j = 0; j < 10; ++j) {
            int e = q * 10 + j;
            float acc = __ldg(&pol_b[e]);
#pragma unroll
            for (int k = 0; k < HID; ++k) acc = fmaf(zr[k], polw[k * NEXP + e], acc);
            lg[j] = acc;
        }

        const float NEG_INF = __int_as_float(0xff800000);
        float best = NEG_INF; int bestE = 0x7fffffff; float m = NEG_INF;
#pragma unroll
        for (int j = 0; j < 10; ++j) {
            int e = q * 10 + j;
            float g = jax_gumbel32((u32)(b * NEXP + e));
            float y = lg[j] + g;
            if (y > best) { best = y; bestE = e; }
            m = fmaxf(m, lg[j]);
        }
#pragma unroll
        for (int off = 1; off < 4; off <<= 1) {
            float ob = __shfl_xor_sync(0xffffffffu, best,  off, 4);
            int   oe = __shfl_xor_sync(0xffffffffu, bestE, off, 4);
            float om = __shfl_xor_sync(0xffffffffu, m,     off, 4);
            if (ob > best || (ob == best && oe < bestE)) { best = ob; bestE = oe; }
            m = fmaxf(m, om);
        }
        float s = 0.0f;
#pragma unroll
        for (int j = 0; j < 10; ++j) s += expf(lg[j] - m);
#pragma unroll
        for (int off = 1; off < 4; off <<= 1) s += __shfl_xor_sync(0xffffffffu, s, off, 4);
#pragma unroll
        for (int j = 0; j < 10; ++j) {
            int e = q * 10 + j;
            out_probs[(size_t)b * NEXP + e] = expf(lg[j] - m) / s;
        }
        if (q == 0) { out_act[b] = (float)bestE; acts[r] = bestE; }
    }
    __syncthreads();   // zf/pool dead from here; stages may be written

    // ---- Phase C: double-buffered cp.async W blobs + bf16-split MMA ----
    const int wid = tid >> 5;          // 0..7
    const int mt  = wid & 3;           // m-tile rows mt*16..+16
    const int nh  = wid >> 2;          // n-half cols nh*32..+32
    const int ln  = tid & 31;
    const int g   = ln >> 2;
    const int tg  = ln & 3;

    const char* zhB = smem + ZH_OFF;
    const char* zlB = smem + ZL_OFF;
    const int rowA0 = mt * 16 + g;
    const int rowA1 = rowA0 + 8;

    const u32 st_u32[2] = { (u32)__cvta_generic_to_shared(smem + ST0_OFF),
                            (u32)__cvta_generic_to_shared(smem + ST1_OFF) };

    // prime pipeline: prefetch e=0, e=1
#pragma unroll 1
    for (int p = 0; p < 2; ++p) {
        const unsigned char* src = g_wblob[p];
        for (int i = tid * 16; i < BLOB_BYTES; i += NTHREADS * 16)
            cpasync16(st_u32[p] + i, src + i);
        CP_COMMIT();
    }

    for (int e = 0; e < NEXP; ++e) {
        CP_WAIT1();            // stage[e&1] data arrived
        __syncthreads();

        const char* stg = smem + ((e & 1) ? ST1_OFF : ST0_OFF);
        const char* whB = stg;
        const char* wlB = stg + 10240;
        const float* bias = (const float*)(stg + 20480);

        float c[4][4];
#pragma unroll
        for (int nt = 0; nt < 4; ++nt)
#pragma unroll
            for (int i = 0; i < 4; ++i) c[nt][i] = 0.0f;

#pragma unroll
        for (int s = 0; s < 4; ++s) {               // k16 steps
            const int ko = s * 32 + tg * 8;
            uint2 ah_lo = *(const uint2*)(zhB + rowA0 * KB_STRIDE + ko);
            uint2 ah_hi = *(const uint2*)(zhB + rowA1 * KB_STRIDE + ko);
            uint2 al_lo = *(const uint2*)(zlB + rowA0 * KB_STRIDE + ko);
            uint2 al_hi = *(const uint2*)(zlB + rowA1 * KB_STRIDE + ko);
#pragma unroll
            for (int nt = 0; nt < 4; ++nt) {
                int n = nh * 32 + nt * 8 + g;
                uint2 bh = *(const uint2*)(whB + n * KB_STRIDE + ko);
                uint2 bl = *(const uint2*)(wlB + n * KB_STRIDE + ko);
                mma_bf16(c[nt], ah_lo.x, ah_hi.x, ah_lo.y, ah_hi.y, bh.x, bh.y);
                mma_bf16(c[nt], ah_lo.x, ah_hi.x, ah_lo.y, ah_hi.y, bl.x, bl.y);
                mma_bf16(c[nt], al_lo.x, al_hi.x, al_lo.y, al_hi.y, bh.x, bh.y);
            }
        }

        // Epilogue: bias + relu + store h
        size_t gb0 = (size_t)(brow + rowA0);
        size_t gb1 = (size_t)(brow + rowA1);
#pragma unroll
        for (int nt = 0; nt < 4; ++nt) {
            int c0i = nh * 32 + nt * 8 + 2 * tg;
            float bb0 = bias[c0i], bb1 = bias[c0i + 1];
            float2 o0, o1;
            o0.x = fmaxf(c[nt][0] + bb0, 0.0f);
            o0.y = fmaxf(c[nt][1] + bb1, 0.0f);
            o1.x = fmaxf(c[nt][2] + bb0, 0.0f);
            o1.y = fmaxf(c[nt][3] + bb1, 0.0f);
            *(float2*)&out_h[(gb0 * NEXP + e) * HID + c0i] = o0;
            *(float2*)&out_h[(gb1 * NEXP + e) * HID + c0i] = o1;
        }

        __syncthreads();       // all warps done reading stage[e&1]
        if (e + 2 < NEXP) {    // prefetch e+2 into the stage just freed
            const unsigned char* src = g_wblob[e + 2];
            for (int i = tid * 16; i < BLOB_BYTES; i += NTHREADS * 16)
                cpasync16(st_u32[e & 1] + i, src + i);
        }
        CP_COMMIT();           // exactly one group per iteration (may be empty)
    }

    // ---- Phase D: out = h[b, action] @ dec_w + dec_b (readback of own rows) ----
    if (tid < ROWS) {
        const int r = tid;
        const int b = brow + r;
        const int a = acts[r];
        const float* hrow = &out_h[((size_t)b * NEXP + a) * HID];
        float a0 = __ldg(&dec_b[0]), a1 = __ldg(&dec_b[1]), a2 = __ldg(&dec_b[2]),
              a3 = __ldg(&dec_b[3]), a4 = __ldg(&dec_b[4]);
        for (int k = 0; k < HID; ++k) {
            float hv = hrow[k];
            a0 = fmaf(hv, __ldg(&dec_w[k * OUTD + 0]), a0);
            a1 = fmaf(hv, __ldg(&dec_w[k * OUTD + 1]), a1);
            a2 = fmaf(hv, __ldg(&dec_w[k * OUTD + 2]), a2);
            a3 = fmaf(hv, __ldg(&dec_w[k * OUTD + 3]), a3);
            a4 = fmaf(hv, __ldg(&dec_w[k * OUTD + 4]), a4);
        }
        size_t ob = (size_t)b * OUTD;
        out_out[ob + 0] = a0; out_out[ob + 1] = a1; out_out[ob + 2] = a2;
        out_out[ob + 3] = a3; out_out[ob + 4] = a4;
    }
}

// ---------------------------------------------------------------------------
extern "C" void kernel_launch(void* const* d_in, const int* in_sizes, int n_in,
                              void* d_out, int out_size) {
    const float* x      = (const float*)d_in[0];
    const float* enc_w  = (const float*)d_in[1];
    const float* enc_b  = (const float*)d_in[2];
    const float* triz_w = (const float*)d_in[3];
    const float* triz_b = (const float*)d_in[4];
    const float* pol_w  = (const float*)d_in[5];
    const float* pol_b  = (const float*)d_in[6];
    const float* dec_w  = (const float*)d_in[7];
    const float* dec_b  = (const float*)d_in[8];
    float* out = (float*)d_out;

    prep_kernel<<<dim3(NEXP, 4), 256>>>(triz_w, triz_b);

    cudaFuncSetAttribute(trizrl_kernel,
                         cudaFuncAttributeMaxDynamicSharedMemorySize, SMEM_TOTAL);
    trizrl_kernel<<<NBLK, NTHREADS, SMEM_TOTAL>>>(x, enc_w, enc_b,
                                                  pol_w, pol_b, dec_w, dec_b, out);
}

// round 14
// speedup vs baseline: 1.7804x; 1.7804x over previous
#include <cuda_runtime.h>
#include <cuda_bf16.h>

#define BATCH    131072
#define INP      5
#define HID      64
#define NEXP     40
#define OUTD     5
#define ROWS     64               // batch rows per block
#define NTHREADS 256
#define NBLK     (BATCH / ROWS)   // 2048

// Per-expert precomputed blob: wh[64][80]bf16 (10240B) | wl (10240B) | bias 64 f32 (256B)
#define BLOB_BYTES 20736
#define KB_STRIDE  160            // bf16 row stride BYTES (80 halves)

// ---- dynamic smem layout (bytes) ----
// [0, 20480): zh(10240)+zl(10240) during Phases A/B + A-frag load;
//             reused as epilogue staging EP (64 rows * 68 floats = 17408B) in Phase C.
#define ZH_OFF   0
#define ZL_OFF   10240
#define EP_OFF   0
#define EP_STRIDE 68              // floats per staged h row
#define ST0_OFF  20480            // W stage 0 (overlaid by zf in Phase A/B)
#define ST1_OFF  41216            // W stage 1 (overlaid by pool in Phase A/B)
#define ACTS_OFF 61952
#define SMEM_TOTAL 62208
#define ZF_STRIDE 66              // fp32 z row stride (floats); zf at ST0 (16896B < 20736)

typedef unsigned int u32;

__device__ __align__(16) unsigned char g_wblob[NEXP][BLOB_BYTES];

// k-permutation: within each k16 block store halves in order (2t,2t+1,2t+8,2t+9)
// so fragment pairs (a0,a2)/(b0,b1) are 8B-contiguous -> one LDS.64.
__device__ __forceinline__ int kperm(int k) {
    return (k & 48) | ((k & 6) << 1) | ((k & 8) >> 2) | (k & 1);
}

__device__ __forceinline__ void mma_bf16(float* c, u32 a0, u32 a1, u32 a2, u32 a3,
                                         u32 b0, u32 b1) {
    asm volatile(
        "mma.sync.aligned.m16n8k16.row.col.f32.bf16.bf16.f32 "
        "{%0,%1,%2,%3}, {%4,%5,%6,%7}, {%8,%9}, {%0,%1,%2,%3};"
        : "+f"(c[0]), "+f"(c[1]), "+f"(c[2]), "+f"(c[3])
        : "r"(a0), "r"(a1), "r"(a2), "r"(a3), "r"(b0), "r"(b1));
}

__device__ __forceinline__ void cpasync16(u32 dst, const void* src) {
    asm volatile("cp.async.cg.shared.global [%0], [%1], 16;" :: "r"(dst), "l"(src));
}
#define CP_COMMIT() asm volatile("cp.async.commit_group;")
#define CP_WAIT1()  asm volatile("cp.async.wait_group 1;")

// ---------------------------------------------------------------------------
// JAX threefry2x32, key = jax.random.key(1) -> (0,1); partitionable counters.
// ---------------------------------------------------------------------------
__device__ __forceinline__ u32 rotl32(u32 x, int d) { return (x << d) | (x >> (32 - d)); }

__device__ __forceinline__ void threefry2x32_key01(u32 c0, u32 c1, u32& o0, u32& o1) {
    const u32 ks0 = 0u, ks1 = 1u, ks2 = 0x1BD11BDBu;
    u32 x0 = c0 + ks0, x1 = c1 + ks1;
#define TFR(r) { x0 += x1; x1 = rotl32(x1, (r)); x1 ^= x0; }
    TFR(13) TFR(15) TFR(26) TFR(6)   x0 += ks1; x1 += ks2 + 1u;
    TFR(17) TFR(29) TFR(16) TFR(24)  x0 += ks2; x1 += ks0 + 2u;
    TFR(13) TFR(15) TFR(26) TFR(6)   x0 += ks0; x1 += ks1 + 3u;
    TFR(17) TFR(29) TFR(16) TFR(24)  x0 += ks1; x1 += ks2 + 4u;
    TFR(13) TFR(15) TFR(26) TFR(6)   x0 += ks2; x1 += ks0 + 5u;
#undef TFR
    o0 = x0; o1 = x1;
}

__device__ __forceinline__ float jax_gumbel32(u32 idx) {
    u32 a, b;
    threefry2x32_key01(0u, idx, a, b);
    u32 bits = a ^ b;
    float f = __uint_as_float(0x3f800000u | (bits >> 9)) - 1.0f;
    float u = fmaxf(f, 1.17549435e-38f);
    return -logf(-logf(u));
}

// ---------------------------------------------------------------------------
// Prep kernel: triz_w -> per-expert blob (bf16 hi/lo split, transposed [f][k],
// k-permuted) + bias. Runs once per launch; deterministic.
// ---------------------------------------------------------------------------
__global__ void prep_kernel(const float* __restrict__ triz_w,
                            const float* __restrict__ triz_b) {
    const int e = blockIdx.x;
    const int q = blockIdx.y;          // k-quarter
    unsigned char* blob = g_wblob[e];
    __nv_bfloat16* wh = (__nv_bfloat16*)blob;
    __nv_bfloat16* wl = (__nv_bfloat16*)(blob + 10240);
    const float* we = triz_w + (size_t)e * HID * HID;

    for (int idx = q * 1024 + threadIdx.x; idx < (q + 1) * 1024; idx += 256) {
        int k = idx >> 6, f = idx & 63;
        float v = we[k * HID + f];
        __nv_bfloat16 hi = __float2bfloat16(v);
        __nv_bfloat16 lo = __float2bfloat16(v - __bfloat162float(hi));
        int off = f * 80 + kperm(k);
        wh[off] = hi;
        wl[off] = lo;
    }
    if (q == 0 && threadIdx.x < HID)
        ((float*)(blob + 20480))[threadIdx.x] = triz_b[e * HID + threadIdx.x];
}

// ---------------------------------------------------------------------------
__global__ __launch_bounds__(NTHREADS, 3)
void trizrl_kernel(const float* __restrict__ x,
                   const float* __restrict__ enc_w, const float* __restrict__ enc_b,
                   const float* __restrict__ pol_w, const float* __restrict__ pol_b,
                   const float* __restrict__ dec_w, const float* __restrict__ dec_b,
                   float* __restrict__ out) {
    extern __shared__ __align__(16) char smem[];
    __nv_bfloat16* zh   = (__nv_bfloat16*)(smem + ZH_OFF);
    __nv_bfloat16* zl   = (__nv_bfloat16*)(smem + ZL_OFF);
    float*         ep   = (float*)(smem + EP_OFF);     // Phase C epilogue staging
    float*         zf   = (float*)(smem + ST0_OFF);    // Phase A/B only
    float*         pool = (float*)(smem + ST1_OFF);    // Phase A/B only
    int*           acts = (int*)(smem + ACTS_OFF);

    float* polw = pool;          // [0:2560)
    float* xs   = pool + 2560;   // [2560:2880)

    // Output: concat(out[B,5], probs[B,40], actions[B], h[B,40,64]) fp32
    float* out_out   = out;
    float* out_probs = out + (size_t)BATCH * OUTD;
    float* out_act   = out_probs + (size_t)BATCH * NEXP;
    float* out_h     = out_act + (size_t)BATCH;

    const int tid  = threadIdx.x;
    const int blk  = blockIdx.x;
    const int brow = blk * ROWS;

    for (int i = tid; i < ROWS * INP; i += NTHREADS)
        xs[i] = x[(size_t)brow * INP + i];
    for (int i = tid; i < HID * NEXP; i += NTHREADS) polw[i] = pol_w[i];
    __syncthreads();

    // ---- Phase A: z = tanh(x@enc_w+enc_b) -> zf (fp32) + zh/zl (bf16 split) ----
    {
        const int j  = tid & (HID - 1);
        const int r0 = tid >> 6;          // 0..3
        const int pj = kperm(j);
        float ew0 = __ldg(&enc_w[0 * HID + j]);
        float ew1 = __ldg(&enc_w[1 * HID + j]);
        float ew2 = __ldg(&enc_w[2 * HID + j]);
        float ew3 = __ldg(&enc_w[3 * HID + j]);
        float ew4 = __ldg(&enc_w[4 * HID + j]);
        float eb  = __ldg(&enc_b[j]);
#pragma unroll
        for (int it = 0; it < ROWS / 4; ++it) {
            int r = it * 4 + r0;
            const float* xr = &xs[r * INP];
            float a = eb;
            a = fmaf(xr[0], ew0, a);
            a = fmaf(xr[1], ew1, a);
            a = fmaf(xr[2], ew2, a);
            a = fmaf(xr[3], ew3, a);
            a = fmaf(xr[4], ew4, a);
            float zv = tanhf(a);
            zf[r * ZF_STRIDE + j] = zv;
            __nv_bfloat16 hi = __float2bfloat16(zv);
            __nv_bfloat16 lo = __float2bfloat16(zv - __bfloat162float(hi));
            zh[r * 80 + pj] = hi;
            zl[r * 80 + pj] = lo;
        }
    }
    __syncthreads();

    // ---- Phase B: logits (exact fp32), gumbel-max categorical, softmax probs ----
    {
        const int r = tid >> 2;
        const int q = tid & 3;
        const int b = brow + r;
        const float* zr = &zf[r * ZF_STRIDE];

        float lg[10];
#pragma unroll
        for (int j = 0; j < 10; ++j) {
            int e = q * 10 + j;
            float acc = __ldg(&pol_b[e]);
#pragma unroll
            for (int k = 0; k < HID; ++k) acc = fmaf(zr[k], polw[k * NEXP + e], acc);
            lg[j] = acc;
        }

        const float NEG_INF = __int_as_float(0xff800000);
        float best = NEG_INF; int bestE = 0x7fffffff; float m = NEG_INF;
#pragma unroll
        for (int j = 0; j < 10; ++j) {
            int e = q * 10 + j;
            float g = jax_gumbel32((u32)(b * NEXP + e));
            float y = lg[j] + g;
            if (y > best) { best = y; bestE = e; }
            m = fmaxf(m, lg[j]);
        }
#pragma unroll
        for (int off = 1; off < 4; off <<= 1) {
            float ob = __shfl_xor_sync(0xffffffffu, best,  off, 4);
            int   oe = __shfl_xor_sync(0xffffffffu, bestE, off, 4);
            float om = __shfl_xor_sync(0xffffffffu, m,     off, 4);
            if (ob > best || (ob == best && oe < bestE)) { best = ob; bestE = oe; }
            m = fmaxf(m, om);
        }
        float s = 0.0f;
#pragma unroll
        for (int j = 0; j < 10; ++j) s += expf(lg[j] - m);
#pragma unroll
        for (int off = 1; off < 4; off <<= 1) s += __shfl_xor_sync(0xffffffffu, s, off, 4);
#pragma unroll
        for (int j = 0; j < 10; ++j) {
            int e = q * 10 + j;
            out_probs[(size_t)b * NEXP + e] = expf(lg[j] - m) / s;
        }
        if (q == 0) { out_act[b] = (float)bestE; acts[r] = bestE; }
    }
    __syncthreads();   // zf/pool dead from here; W stages may be written

    // ---- Phase C setup: warp/lane tiling ----
    const int wid = tid >> 5;          // 0..7
    const int mt  = wid & 3;           // m-tile rows mt*16..+16
    const int nh  = wid >> 2;          // n-half cols nh*32..+32
    const int ln  = tid & 31;
    const int g   = ln >> 2;
    const int tg  = ln & 3;

    const char* zhB = smem + ZH_OFF;
    const char* zlB = smem + ZL_OFF;
    const int rowA0 = mt * 16 + g;
    const int rowA1 = rowA0 + 8;

    // A fragments are expert-invariant: load ONCE into registers.
    uint2 AH[4][2], AL[4][2];
#pragma unroll
    for (int s = 0; s < 4; ++s) {
        const int ko = s * 32 + tg * 8;
        AH[s][0] = *(const uint2*)(zhB + rowA0 * KB_STRIDE + ko);
        AH[s][1] = *(const uint2*)(zhB + rowA1 * KB_STRIDE + ko);
        AL[s][0] = *(const uint2*)(zlB + rowA0 * KB_STRIDE + ko);
        AL[s][1] = *(const uint2*)(zlB + rowA1 * KB_STRIDE + ko);
    }
    // zh/zl region is now dead -> becomes epilogue staging `ep`.
    // First write to ep happens after the e=0 top-of-loop __syncthreads(),
    // which orders it after every thread's A-fragment loads above.

    const u32 st_u32[2] = { (u32)__cvta_generic_to_shared(smem + ST0_OFF),
                            (u32)__cvta_generic_to_shared(smem + ST1_OFF) };

    // prime pipeline: prefetch e=0, e=1
#pragma unroll 1
    for (int p = 0; p < 2; ++p) {
        const unsigned char* src = g_wblob[p];
        for (int i = tid * 16; i < BLOB_BYTES; i += NTHREADS * 16)
            cpasync16(st_u32[p] + i, src + i);
        CP_COMMIT();
    }

    for (int e = 0; e < NEXP; ++e) {
        CP_WAIT1();            // stage[e&1] arrived
        __syncthreads();       // also: ep staging free (prev iter's readers done)

        const char* stg = smem + ((e & 1) ? ST1_OFF : ST0_OFF);
        const char* whB = stg;
        const char* wlB = stg + 10240;
        const float* bias = (const float*)(stg + 20480);

        float c[4][4];
#pragma unroll
        for (int nt = 0; nt < 4; ++nt)
#pragma unroll
            for (int i = 0; i < 4; ++i) c[nt][i] = 0.0f;

#pragma unroll
        for (int s = 0; s < 4; ++s) {               // k16 steps
            const int ko = s * 32 + tg * 8;
#pragma unroll
            for (int nt = 0; nt < 4; ++nt) {
                int n = nh * 32 + nt * 8 + g;
                uint2 bh = *(const uint2*)(whB + n * KB_STRIDE + ko);
                uint2 bl = *(const uint2*)(wlB + n * KB_STRIDE + ko);
                mma_bf16(c[nt], AH[s][0].x, AH[s][1].x, AH[s][0].y, AH[s][1].y, bh.x, bh.y);
                mma_bf16(c[nt], AH[s][0].x, AH[s][1].x, AH[s][0].y, AH[s][1].y, bl.x, bl.y);
                mma_bf16(c[nt], AL[s][0].x, AL[s][1].x, AL[s][0].y, AL[s][1].y, bh.x, bh.y);
            }
        }

        // Epilogue 1: bias + relu -> smem staging (per-warp disjoint slabs)
#pragma unroll
        for (int nt = 0; nt < 4; ++nt) {
            int c0i = nh * 32 + nt * 8 + 2 * tg;
            float bb0 = bias[c0i], bb1 = bias[c0i + 1];
            float2 o0, o1;
            o0.x = fmaxf(c[nt][0] + bb0, 0.0f);
            o0.y = fmaxf(c[nt][1] + bb1, 0.0f);
            o1.x = fmaxf(c[nt][2] + bb0, 0.0f);
            o1.y = fmaxf(c[nt][3] + bb1, 0.0f);
            *(float2*)&ep[rowA0 * EP_STRIDE + c0i] = o0;
            *(float2*)&ep[rowA1 * EP_STRIDE + c0i] = o1;
        }
        __syncthreads();

        // Epilogue 2: coalesced h stores — full 256B rows as float4.
        {
            const int rbase = tid >> 4;          // 0..15
            const int col4  = (tid & 15) * 4;    // 0,4,...,60
#pragma unroll
            for (int it = 0; it < 4; ++it) {
                int row = it * 16 + rbase;
                float4 v = *(const float4*)&ep[row * EP_STRIDE + col4];
                *(float4*)&out_h[((size_t)(brow + row) * NEXP + e) * HID + col4] = v;
            }
        }

        // Prefetch e+2 into the stage just freed (all MMA reads done at the
        // post-STS __syncthreads above).
        if (e + 2 < NEXP) {
            const unsigned char* src = g_wblob[e + 2];
            for (int i = tid * 16; i < BLOB_BYTES; i += NTHREADS * 16)
                cpasync16(st_u32[e & 1] + i, src + i);
        }
        CP_COMMIT();           // exactly one group per iteration (may be empty)
    }
    __syncthreads();

    // ---- Phase D: out = h[b, action] @ dec_w + dec_b (readback of own rows) ----
    if (tid < ROWS) {
        const int r = tid;
        const int b = brow + r;
        const int a = acts[r];
        const float* hrow = &out_h[((size_t)b * NEXP + a) * HID];
        float a0 = __ldg(&dec_b[0]), a1 = __ldg(&dec_b[1]), a2 = __ldg(&dec_b[2]),
              a3 = __ldg(&dec_b[3]), a4 = __ldg(&dec_b[4]);
        for (int k = 0; k < HID; ++k) {
            float hv = hrow[k];
            a0 = fmaf(hv, __ldg(&dec_w[k * OUTD + 0]), a0);
            a1 = fmaf(hv, __ldg(&dec_w[k * OUTD + 1]), a1);
            a2 = fmaf(hv, __ldg(&dec_w[k * OUTD + 2]), a2);
            a3 = fmaf(hv, __ldg(&dec_w[k * OUTD + 3]), a3);
            a4 = fmaf(hv, __ldg(&dec_w[k * OUTD + 4]), a4);
        }
        size_t ob = (size_t)b * OUTD;
        out_out[ob + 0] = a0; out_out[ob + 1] = a1; out_out[ob + 2] = a2;
        out_out[ob + 3] = a3; out_out[ob + 4] = a4;
    }
}

// ---------------------------------------------------------------------------
extern "C" void kernel_launch(void* const* d_in, const int* in_sizes, int n_in,
                              void* d_out, int out_size) {
    const float* x      = (const float*)d_in[0];
    const float* enc_w  = (const float*)d_in[1];
    const float* enc_b  = (const float*)d_in[2];
    const float* triz_w = (const float*)d_in[3];
    const float* triz_b = (const float*)d_in[4];
    const float* pol_w  = (const float*)d_in[5];
    const float* pol_b  = (const float*)d_in[6];
    const float* dec_w  = (const float*)d_in[7];
    const float* dec_b  = (const float*)d_in[8];
    float* out = (float*)d_out;

    prep_kernel<<<dim3(NEXP, 4), 256>>>(triz_w, triz_b);

    cudaFuncSetAttribute(trizrl_kernel,
                         cudaFuncAttributeMaxDynamicSharedMemorySize, SMEM_TOTAL);
    trizrl_kernel<<<NBLK, NTHREADS, SMEM_TOTAL>>>(x, enc_w, enc_b,
                                                  pol_w, pol_b, dec_w, dec_b, out);
}